// round 1
// baseline (speedup 1.0000x reference)
#include <cuda_runtime.h>
#include <cstdint>

// ---------------------------------------------------------------------------
// Problem constants: B=4, NQ=NK=2048, DQ=DK=DV=1024, H=8, d=128
// ---------------------------------------------------------------------------
#define NROWS   8192          // B*NQ
#define DMODEL  1024
#define NKEYS   2048
#define NHEAD   8
#define DHEAD   128
#define NBATCH  4
#define NBH     32            // NBATCH*NHEAD

// Scratch (device globals are the sanctioned allocation-free scratch path)
__device__ float g_qb [NROWS * DMODEL];
__device__ float g_kb [NROWS * DMODEL];
__device__ float g_vb [NROWS * DMODEL];
__device__ float g_att[NROWS * DMODEL];
__device__ float g_x0 [NROWS * DMODEL];
__device__ float g_S  [(size_t)NBH * NKEYS * NKEYS];   // 537 MB logits scratch

// ---------------------------------------------------------------------------
// helpers
// ---------------------------------------------------------------------------
__device__ __forceinline__ uint32_t f2tf32(float x) {
    uint32_t u;
    asm("cvt.rna.tf32.f32 %0, %1;" : "=r"(u) : "f"(x));
    return u;
}

__device__ __forceinline__ float warpMax(float v) {
    #pragma unroll
    for (int o = 16; o; o >>= 1) v = fmaxf(v, __shfl_xor_sync(0xFFFFFFFFu, v, o));
    return v;
}
__device__ __forceinline__ float warpSum(float v) {
    #pragma unroll
    for (int o = 16; o; o >>= 1) v += __shfl_xor_sync(0xFFFFFFFFu, v, o);
    return v;
}

// ---------------------------------------------------------------------------
// Generic TF32 GEMM:  C[M,N] = epi( A[M,K] * op(B) )
//   TRANSB=true : B stored [N,K] row-major (k contiguous)  -> C = A*B^T
//   TRANSB=false: B stored [K,N] row-major (n contiguous)  -> C = A*B
// Batched over blockIdx.z with offset = (z/8)*Out + (z%8)*In per operand.
// EPI: 0 = +bias ; 1 = *alpha ; 2 = +Res ; 3 = Res + relu(acc + bias)
// All of M%128==0, N%128==0, K%32==0 hold for every call site -> no bounds.
// ---------------------------------------------------------------------------
template<int EPI, bool TRANSB>
__global__ __launch_bounds__(256)
void gemm_kernel(const float* __restrict__ A, const float* __restrict__ B,
                 float* __restrict__ C,
                 const float* __restrict__ bias, const float* __restrict__ Res,
                 int K, int lda, int ldb, int ldc,
                 long aOut, long aIn, long bOut, long bIn,
                 long cOut, long cIn, long rOut, long rIn,
                 float alpha)
{
    __shared__ float As[128][36];   // BK=32 + pad 4
    __shared__ float Bs[32][132];   // BN=128 + pad 4

    const int z = blockIdx.z, zb = z >> 3, zh = z & 7;
    A += zb * aOut + zh * aIn;
    B += zb * bOut + zh * bIn;
    C += zb * cOut + zh * cIn;
    if (EPI == 2 || EPI == 3) Res += zb * rOut + zh * rIn;

    const int m0 = blockIdx.y * 128, n0 = blockIdx.x * 128;
    const int tid  = threadIdx.x;
    const int warp = tid >> 5, lane = tid & 31;
    const int wm = (warp >> 2) * 64, wn = (warp & 3) * 32;
    const int g  = lane >> 2, tg = lane & 3;

    float acc[4][4][4];
    #pragma unroll
    for (int i = 0; i < 4; i++)
        #pragma unroll
        for (int j = 0; j < 4; j++)
            #pragma unroll
            for (int e = 0; e < 4; e++) acc[i][j][e] = 0.f;

    for (int k0 = 0; k0 < K; k0 += 32) {
        // ---- stage A tile [128 x 32] (tf32-converted) ----
        #pragma unroll
        for (int i = 0; i < 4; i++) {
            int idx = tid + i * 256;
            int r = idx >> 3, kq = (idx & 7) << 2;
            float4 va = *(const float4*)(A + (long)(m0 + r) * lda + (k0 + kq));
            float4 t;
            t.x = __uint_as_float(f2tf32(va.x));
            t.y = __uint_as_float(f2tf32(va.y));
            t.z = __uint_as_float(f2tf32(va.z));
            t.w = __uint_as_float(f2tf32(va.w));
            *(float4*)&As[r][kq] = t;
        }
        // ---- stage B tile into Bs[k][n] ----
        if (TRANSB) {
            #pragma unroll
            for (int i = 0; i < 4; i++) {
                int idx = tid + i * 256;
                int n = idx >> 3, kq = (idx & 7) << 2;
                float4 vb = *(const float4*)(B + (long)(n0 + n) * ldb + (k0 + kq));
                Bs[kq + 0][n] = __uint_as_float(f2tf32(vb.x));
                Bs[kq + 1][n] = __uint_as_float(f2tf32(vb.y));
                Bs[kq + 2][n] = __uint_as_float(f2tf32(vb.z));
                Bs[kq + 3][n] = __uint_as_float(f2tf32(vb.w));
            }
        } else {
            #pragma unroll
            for (int i = 0; i < 4; i++) {
                int idx = tid + i * 256;
                int kr = idx >> 5, nq = (idx & 31) << 2;
                float4 vb = *(const float4*)(B + (long)(k0 + kr) * ldb + (n0 + nq));
                float4 t;
                t.x = __uint_as_float(f2tf32(vb.x));
                t.y = __uint_as_float(f2tf32(vb.y));
                t.z = __uint_as_float(f2tf32(vb.z));
                t.w = __uint_as_float(f2tf32(vb.w));
                *(float4*)&Bs[kr][nq] = t;
            }
        }
        __syncthreads();

        // ---- compute: 4 k-steps of m16n8k8 ----
        #pragma unroll
        for (int ks = 0; ks < 4; ks++) {
            const int kk = ks * 8;
            uint32_t af[4][4], bf[4][2];
            #pragma unroll
            for (int mf = 0; mf < 4; mf++) {
                int r = wm + mf * 16 + g;
                af[mf][0] = __float_as_uint(As[r    ][kk + tg    ]);
                af[mf][1] = __float_as_uint(As[r + 8][kk + tg    ]);
                af[mf][2] = __float_as_uint(As[r    ][kk + tg + 4]);
                af[mf][3] = __float_as_uint(As[r + 8][kk + tg + 4]);
            }
            #pragma unroll
            for (int nf = 0; nf < 4; nf++) {
                int c = wn + nf * 8 + g;
                bf[nf][0] = __float_as_uint(Bs[kk + tg    ][c]);
                bf[nf][1] = __float_as_uint(Bs[kk + tg + 4][c]);
            }
            #pragma unroll
            for (int mf = 0; mf < 4; mf++)
                #pragma unroll
                for (int nf = 0; nf < 4; nf++)
                    asm volatile(
                        "mma.sync.aligned.m16n8k8.row.col.f32.tf32.tf32.f32 "
                        "{%0,%1,%2,%3}, {%4,%5,%6,%7}, {%8,%9}, {%0,%1,%2,%3};"
                        : "+f"(acc[mf][nf][0]), "+f"(acc[mf][nf][1]),
                          "+f"(acc[mf][nf][2]), "+f"(acc[mf][nf][3])
                        : "r"(af[mf][0]), "r"(af[mf][1]), "r"(af[mf][2]), "r"(af[mf][3]),
                          "r"(bf[nf][0]), "r"(bf[nf][1]));
        }
        __syncthreads();
    }

    // ---- epilogue ----
    #pragma unroll
    for (int mf = 0; mf < 4; mf++) {
        #pragma unroll
        for (int nf = 0; nf < 4; nf++) {
            int r = m0 + wm + mf * 16 + g;
            int c = n0 + wn + nf * 8 + 2 * tg;
            #pragma unroll
            for (int e = 0; e < 4; e++) {
                int rr = r + (e >> 1) * 8;
                int cc = c + (e & 1);
                float v = acc[mf][nf][e];
                if (EPI == 0)      { v += bias[cc]; }
                else if (EPI == 1) { v *= alpha; }
                else if (EPI == 2) { v += Res[(long)rr * ldc + cc]; }
                else if (EPI == 3) { v += bias[cc]; v = fmaxf(v, 0.f);
                                     v += Res[(long)rr * ldc + cc]; }
                C[(long)rr * ldc + cc] = v;
            }
        }
    }
}

// ---------------------------------------------------------------------------
// Row softmax over S[row, 0:2048], in place. 256 threads, 8 elems/thread.
// ---------------------------------------------------------------------------
__global__ __launch_bounds__(256)
void softmax_kernel(float* __restrict__ S)
{
    float* row = S + (size_t)blockIdx.x * NKEYS;
    const int tid = threadIdx.x;
    float v[8];
    float m = -1e30f;
    #pragma unroll
    for (int i = 0; i < 8; i++) { v[i] = row[i * 256 + tid]; m = fmaxf(m, v[i]); }
    m = warpMax(m);
    __shared__ float sm[8], ss[8];
    if ((tid & 31) == 0) sm[tid >> 5] = m;
    __syncthreads();
    float bm = fmaxf(fmaxf(fmaxf(sm[0], sm[1]), fmaxf(sm[2], sm[3])),
                     fmaxf(fmaxf(sm[4], sm[5]), fmaxf(sm[6], sm[7])));
    float s = 0.f;
    #pragma unroll
    for (int i = 0; i < 8; i++) { v[i] = __expf(v[i] - bm); s += v[i]; }
    s = warpSum(s);
    if ((tid & 31) == 0) ss[tid >> 5] = s;
    __syncthreads();
    float tot = ((ss[0] + ss[1]) + (ss[2] + ss[3])) + ((ss[4] + ss[5]) + (ss[6] + ss[7]));
    float inv = 1.f / tot;
    #pragma unroll
    for (int i = 0; i < 8; i++) row[i * 256 + tid] = v[i] * inv;
}

// ---------------------------------------------------------------------------
// LayerNorm over rows of width 1024. 256 threads, 4 elems/thread.
// ---------------------------------------------------------------------------
__global__ __launch_bounds__(256)
void ln_kernel(const float* __restrict__ X, float* __restrict__ Y,
               const float* __restrict__ gam, const float* __restrict__ bet)
{
    const float* x = X + (size_t)blockIdx.x * DMODEL;
    float*       y = Y + (size_t)blockIdx.x * DMODEL;
    const int tid = threadIdx.x;
    float v[4];
    float s = 0.f, sq = 0.f;
    #pragma unroll
    for (int i = 0; i < 4; i++) {
        v[i] = x[i * 256 + tid];
        s  += v[i];
        sq += v[i] * v[i];
    }
    s  = warpSum(s);
    sq = warpSum(sq);
    __shared__ float a1[8], a2[8];
    if ((tid & 31) == 0) { a1[tid >> 5] = s; a2[tid >> 5] = sq; }
    __syncthreads();
    float S1 = ((a1[0] + a1[1]) + (a1[2] + a1[3])) + ((a1[4] + a1[5]) + (a1[6] + a1[7]));
    float S2 = ((a2[0] + a2[1]) + (a2[2] + a2[3])) + ((a2[4] + a2[5]) + (a2[6] + a2[7]));
    const float invn = 1.f / (float)DMODEL;
    float mu  = S1 * invn;
    float var = S2 * invn - mu * mu;
    float rs  = rsqrtf(var + 1e-5f);
    #pragma unroll
    for (int i = 0; i < 4; i++) {
        int c = i * 256 + tid;
        y[c] = (v[i] - mu) * rs * gam[c] + bet[c];
    }
}

// ---------------------------------------------------------------------------
// launch
// ---------------------------------------------------------------------------
extern "C" void kernel_launch(void* const* d_in, const int* in_sizes, int n_in,
                              void* d_out, int out_size)
{
    (void)in_sizes; (void)n_in; (void)out_size;
    const float* Q  = (const float*)d_in[0];
    const float* K_ = (const float*)d_in[1];
    const float* Wq = (const float*)d_in[2];
    const float* bq = (const float*)d_in[3];
    const float* Wk = (const float*)d_in[4];
    const float* bk = (const float*)d_in[5];
    const float* Wv = (const float*)d_in[6];
    const float* bv = (const float*)d_in[7];
    const float* Wo = (const float*)d_in[8];
    const float* bo = (const float*)d_in[9];
    const float* g0 = (const float*)d_in[10];
    const float* b0 = (const float*)d_in[11];
    const float* g1 = (const float*)d_in[12];
    const float* b1 = (const float*)d_in[13];
    float* out = (float*)d_out;

    float *qb, *kb, *vb, *att, *x0, *S;
    cudaGetSymbolAddress((void**)&qb,  g_qb);
    cudaGetSymbolAddress((void**)&kb,  g_kb);
    cudaGetSymbolAddress((void**)&vb,  g_vb);
    cudaGetSymbolAddress((void**)&att, g_att);
    cudaGetSymbolAddress((void**)&x0,  g_x0);
    cudaGetSymbolAddress((void**)&S,   g_S);

    const long PM = (long)NKEYS * DMODEL;     // 2048*1024: per-batch stride in proj bufs
    const long SM = (long)NKEYS * NKEYS;      // 2048*2048: per-(b,h) stride in S
    const float isq = 0.088388347648318447f;  // 1/sqrt(128)

    dim3 blk(256);
    dim3 gp(DMODEL / 128, NROWS / 128, 1);          // (8, 64)

    // 1-3: projections  q/k/v = X @ W^T + b
    gemm_kernel<0, true><<<gp, blk>>>(Q,  Wq, qb, bq, nullptr, DMODEL, DMODEL, DMODEL, DMODEL,
                                      0,0,0,0,0,0,0,0, 1.f);
    gemm_kernel<0, true><<<gp, blk>>>(K_, Wk, kb, bk, nullptr, DMODEL, DMODEL, DMODEL, DMODEL,
                                      0,0,0,0,0,0,0,0, 1.f);
    gemm_kernel<0, true><<<gp, blk>>>(K_, Wv, vb, bv, nullptr, DMODEL, DMODEL, DMODEL, DMODEL,
                                      0,0,0,0,0,0,0,0, 1.f);

    // 4: logits S[b,h] = (q_head @ k_head^T) / sqrt(d)
    dim3 gs(NKEYS / 128, NKEYS / 128, NBH);          // (16, 16, 32)
    gemm_kernel<1, true><<<gs, blk>>>(qb, kb, S, nullptr, nullptr,
                                      DHEAD, DMODEL, DMODEL, NKEYS,
                                      PM, DHEAD,  PM, DHEAD,  8 * SM, SM,  0, 0, isq);

    // 5: row softmax
    softmax_kernel<<<NBH * NKEYS, 256>>>(S);

    // 6: attention out = q + A @ v    (per head, residual with projected q)
    dim3 gav(1, NKEYS / 128, NBH);                   // (1, 16, 32)
    gemm_kernel<2, false><<<gav, blk>>>(S, vb, att, nullptr, qb,
                                        NKEYS, NKEYS, DMODEL, DMODEL,
                                        8 * SM, SM,  PM, DHEAD,  PM, DHEAD,  PM, DHEAD, 1.f);

    // 7: LN0
    ln_kernel<<<NROWS, 256>>>(att, x0, g0, b0);

    // 8: y = x0 + relu(x0 @ Wo^T + bo)   (write into att, which is now free)
    gemm_kernel<3, true><<<gp, blk>>>(x0, Wo, att, bo, x0, DMODEL, DMODEL, DMODEL, DMODEL,
                                      0,0,0,0,0,0,0,0, 1.f);

    // 9: LN1 -> output
    ln_kernel<<<NROWS, 256>>>(att, out, g1, b1);
}

// round 3
// speedup vs baseline: 1.5459x; 1.5459x over previous
#include <cuda_runtime.h>
#include <cstdint>

// ---------------------------------------------------------------------------
// B=4, NQ=NK=2048, D=1024, H=8, d=128
// ---------------------------------------------------------------------------
#define NROWS   8192
#define DMODEL  1024
#define NKEYS   2048
#define NBH     32

__device__ float g_qb [NROWS * DMODEL];
__device__ float g_kb [NROWS * DMODEL];
__device__ float g_vb [NROWS * DMODEL];
__device__ float g_att[NROWS * DMODEL];
__device__ float g_x0 [NROWS * DMODEL];

// ---------------------------------------------------------------------------
// helpers
// ---------------------------------------------------------------------------
__device__ __forceinline__ float tf32r(float x) {
    uint32_t u;
    asm("cvt.rna.tf32.f32 %0, %1;" : "=r"(u) : "f"(x));
    return __uint_as_float(u);
}
__device__ __forceinline__ uint32_t tf32u(float x) {
    uint32_t u;
    asm("cvt.rna.tf32.f32 %0, %1;" : "=r"(u) : "f"(x));
    return u;
}
__device__ __forceinline__ void mma_tf32(float* c, uint32_t a0, uint32_t a1,
                                         uint32_t a2, uint32_t a3,
                                         uint32_t b0, uint32_t b1) {
    asm volatile(
        "mma.sync.aligned.m16n8k8.row.col.f32.tf32.tf32.f32 "
        "{%0,%1,%2,%3}, {%4,%5,%6,%7}, {%8,%9}, {%0,%1,%2,%3};"
        : "+f"(c[0]), "+f"(c[1]), "+f"(c[2]), "+f"(c[3])
        : "r"(a0), "r"(a1), "r"(a2), "r"(a3), "r"(b0), "r"(b1));
}
__device__ __forceinline__ void cp16(void* dst, const void* src) {
    uint32_t d = (uint32_t)__cvta_generic_to_shared(dst);
    asm volatile("cp.async.ca.shared.global [%0], [%1], 16;\n" :: "r"(d), "l"(src));
}
#define CP_COMMIT() asm volatile("cp.async.commit_group;\n")
#define CP_WAIT1()  asm volatile("cp.async.wait_group 1;\n")

__device__ __forceinline__ float warpSum(float v) {
    #pragma unroll
    for (int o = 16; o; o >>= 1) v += __shfl_xor_sync(0xFFFFFFFFu, v, o);
    return v;
}
__device__ __forceinline__ float quadMax(float v) {
    v = fmaxf(v, __shfl_xor_sync(0xFFFFFFFFu, v, 1));
    v = fmaxf(v, __shfl_xor_sync(0xFFFFFFFFu, v, 2));
    return v;
}
__device__ __forceinline__ float quadSum(float v) {
    v += __shfl_xor_sync(0xFFFFFFFFu, v, 1);
    v += __shfl_xor_sync(0xFFFFFFFFu, v, 2);
    return v;
}

// ---------------------------------------------------------------------------
// GEMM: C[8192,1024] = epi( A[8192,1024] @ B^T ), B[1024,1024] row-major n,k.
// cp.async 2-stage double buffer. Both tiles in [row][36] layout (bank-clean:
// stage banks = 4*lane, frag banks = 4g+tg, both bijective mod 32).
// EPI 0: +bias ; EPI 3: Res + relu(acc + bias)
// ---------------------------------------------------------------------------
template<int EPI>
__global__ __launch_bounds__(256, 2)
void gemm_nt(const float* __restrict__ A, const float* __restrict__ B,
             float* __restrict__ C,
             const float* __restrict__ bias, const float* __restrict__ Res)
{
    extern __shared__ float sm[];
    float* As = sm;              // [2][128][36]
    float* Bs = sm + 2 * 128 * 36;
    #define ASM(s,r,c) As[(s)*4608 + (r)*36 + (c)]
    #define BSM(s,r,c) Bs[(s)*4608 + (r)*36 + (c)]

    const int m0 = blockIdx.y * 128, n0 = blockIdx.x * 128;
    const int tid = threadIdx.x;
    const int warp = tid >> 5, lane = tid & 31;
    const int wm = (warp >> 2) * 64, wn = (warp & 3) * 32;
    const int g = lane >> 2, tg = lane & 3;
    const int sr = tid >> 3, skq = (tid & 7) << 2;

    float acc[4][4][4];
    #pragma unroll
    for (int i = 0; i < 4; i++)
        #pragma unroll
        for (int j = 0; j < 4; j++)
            #pragma unroll
            for (int e = 0; e < 4; e++) acc[i][j][e] = 0.f;

    auto stage = [&](int s, int k0) {
        #pragma unroll
        for (int i = 0; i < 4; i++) {
            int r = sr + 32 * i;
            cp16(&ASM(s, r, skq), A + (long)(m0 + r) * DMODEL + k0 + skq);
            cp16(&BSM(s, r, skq), B + (long)(n0 + r) * DMODEL + k0 + skq);
        }
    };

    stage(0, 0);  CP_COMMIT();
    stage(1, 32); CP_COMMIT();

    for (int kt = 0; kt < 32; kt++) {
        CP_WAIT1();
        __syncthreads();
        const int s = kt & 1;
        #pragma unroll
        for (int ks = 0; ks < 4; ks++) {
            const int kk = ks * 8;
            uint32_t af[4][4], bf[4][2];
            #pragma unroll
            for (int mf = 0; mf < 4; mf++) {
                int r = wm + mf * 16 + g;
                af[mf][0] = tf32u(ASM(s, r,     kk + tg));
                af[mf][1] = tf32u(ASM(s, r + 8, kk + tg));
                af[mf][2] = tf32u(ASM(s, r,     kk + tg + 4));
                af[mf][3] = tf32u(ASM(s, r + 8, kk + tg + 4));
            }
            #pragma unroll
            for (int nf = 0; nf < 4; nf++) {
                int c = wn + nf * 8 + g;
                bf[nf][0] = tf32u(BSM(s, c, kk + tg));
                bf[nf][1] = tf32u(BSM(s, c, kk + tg + 4));
            }
            #pragma unroll
            for (int mf = 0; mf < 4; mf++)
                #pragma unroll
                for (int nf = 0; nf < 4; nf++)
                    mma_tf32(acc[mf][nf], af[mf][0], af[mf][1], af[mf][2], af[mf][3],
                             bf[nf][0], bf[nf][1]);
        }
        __syncthreads();
        if (kt < 30) stage(s, (kt + 2) * 32);
        CP_COMMIT();   // commit every iter (empty groups keep wait_group numbering)
    }

    #pragma unroll
    for (int mf = 0; mf < 4; mf++) {
        #pragma unroll
        for (int nf = 0; nf < 4; nf++) {
            int r = m0 + wm + mf * 16 + g;
            int c = n0 + wn + nf * 8 + 2 * tg;
            #pragma unroll
            for (int e = 0; e < 4; e++) {
                int rr = r + (e >> 1) * 8;
                int cc = c + (e & 1);
                float v = acc[mf][nf][e];
                if (EPI == 0) { v += bias[cc]; }
                else          { v += bias[cc]; v = fmaxf(v, 0.f);
                                v += Res[(long)rr * DMODEL + cc]; }
                C[(long)rr * DMODEL + cc] = v;
            }
        }
    }
    #undef ASM
    #undef BSM
}

// ---------------------------------------------------------------------------
// Flash attention: per CTA one (b,h) and 128 q-rows; loop 32 tiles of 64 keys.
// 8 warps; each warp owns 16 full rows -> softmax stats stay in registers.
// out = q + softmax(q k^T / sqrt(d)) v   (residual q read exactly from gmem)
// smem: Qs[128][132] | Ks[64][132] | Vs[64][136] | Ps[128][72]  = 173056 B
// ---------------------------------------------------------------------------
__global__ __launch_bounds__(256, 1)
void flash_kernel(const float* __restrict__ qb, const float* __restrict__ kb,
                  const float* __restrict__ vb, float* __restrict__ att)
{
    extern __shared__ float sm[];
    float* Qs = sm;                      // 128*132
    float* Ks = Qs + 128 * 132;          // 64*132
    float* Vs = Ks + 64 * 132;           // 64*136
    float* Ps = Vs + 64 * 136;           // 128*72

    const int bh = blockIdx.y, zb = bh >> 3, zh = bh & 7;
    const long base = (long)zb * (NKEYS * DMODEL) + zh * 128;
    const float* qp = qb + base + (long)blockIdx.x * 128 * DMODEL;
    const float* kp = kb + base;
    const float* vp = vb + base;
    float*       op = att + base + (long)blockIdx.x * 128 * DMODEL;

    const int tid = threadIdx.x, warp = tid >> 5, lane = tid & 31;
    const int g = lane >> 2, tg = lane & 3;
    const int wr = warp * 16;
    const float isq = 0.088388347648318447f;   // 1/sqrt(128)

    // load Q tile (tf32)
    #pragma unroll
    for (int i = 0; i < 16; i++) {
        int idx = tid + i * 256;
        int r = idx >> 5, cq = (idx & 31) << 2;
        float4 v = *(const float4*)(qp + (long)r * DMODEL + cq);
        Qs[r * 132 + cq + 0] = tf32r(v.x);
        Qs[r * 132 + cq + 1] = tf32r(v.y);
        Qs[r * 132 + cq + 2] = tf32r(v.z);
        Qs[r * 132 + cq + 3] = tf32r(v.w);
    }

    float o[16][4];
    #pragma unroll
    for (int f = 0; f < 16; f++)
        #pragma unroll
        for (int e = 0; e < 4; e++) o[f][e] = 0.f;
    float mrow0 = -1e30f, mrow1 = -1e30f, l0 = 0.f, l1 = 0.f;

    for (int j = 0; j < 32; j++) {
        __syncthreads();                       // prev iter done reading Ks/Vs
        #pragma unroll
        for (int i = 0; i < 8; i++) {
            int idx = tid + i * 256;
            int r = idx >> 5, cq = (idx & 31) << 2;
            const long gro = (long)(j * 64 + r) * DMODEL + cq;
            float4 kv = *(const float4*)(kp + gro);
            Ks[r * 132 + cq + 0] = tf32r(kv.x);
            Ks[r * 132 + cq + 1] = tf32r(kv.y);
            Ks[r * 132 + cq + 2] = tf32r(kv.z);
            Ks[r * 132 + cq + 3] = tf32r(kv.w);
            float4 vv = *(const float4*)(vp + gro);
            Vs[r * 136 + cq + 0] = tf32r(vv.x);
            Vs[r * 136 + cq + 1] = tf32r(vv.y);
            Vs[r * 136 + cq + 2] = tf32r(vv.z);
            Vs[r * 136 + cq + 3] = tf32r(vv.w);
        }
        __syncthreads();

        // ---- S = Q K^T (warp: 16 rows x 64 keys) ----
        float s[8][4];
        #pragma unroll
        for (int nf = 0; nf < 8; nf++)
            #pragma unroll
            for (int e = 0; e < 4; e++) s[nf][e] = 0.f;
        #pragma unroll
        for (int ks = 0; ks < 16; ks++) {
            const int kk = ks * 8;
            uint32_t a0 = __float_as_uint(Qs[(wr + g    ) * 132 + kk + tg]);
            uint32_t a1 = __float_as_uint(Qs[(wr + g + 8) * 132 + kk + tg]);
            uint32_t a2 = __float_as_uint(Qs[(wr + g    ) * 132 + kk + tg + 4]);
            uint32_t a3 = __float_as_uint(Qs[(wr + g + 8) * 132 + kk + tg + 4]);
            #pragma unroll
            for (int nf = 0; nf < 8; nf++) {
                uint32_t b0 = __float_as_uint(Ks[(nf * 8 + g) * 132 + kk + tg]);
                uint32_t b1 = __float_as_uint(Ks[(nf * 8 + g) * 132 + kk + tg + 4]);
                mma_tf32(s[nf], a0, a1, a2, a3, b0, b1);
            }
        }

        // ---- online softmax (rows g and g+8 of this warp) ----
        float tm0 = -1e30f, tm1 = -1e30f;
        #pragma unroll
        for (int nf = 0; nf < 8; nf++) {
            s[nf][0] *= isq; s[nf][1] *= isq; s[nf][2] *= isq; s[nf][3] *= isq;
            tm0 = fmaxf(tm0, fmaxf(s[nf][0], s[nf][1]));
            tm1 = fmaxf(tm1, fmaxf(s[nf][2], s[nf][3]));
        }
        tm0 = quadMax(tm0); tm1 = quadMax(tm1);
        float mn0 = fmaxf(mrow0, tm0), mn1 = fmaxf(mrow1, tm1);
        float sc0 = __expf(mrow0 - mn0), sc1 = __expf(mrow1 - mn1);
        mrow0 = mn0; mrow1 = mn1;
        float ls0 = 0.f, ls1 = 0.f;
        #pragma unroll
        for (int nf = 0; nf < 8; nf++) {
            s[nf][0] = __expf(s[nf][0] - mn0);
            s[nf][1] = __expf(s[nf][1] - mn0);
            s[nf][2] = __expf(s[nf][2] - mn1);
            s[nf][3] = __expf(s[nf][3] - mn1);
            ls0 += s[nf][0] + s[nf][1];
            ls1 += s[nf][2] + s[nf][3];
        }
        l0 = l0 * sc0 + ls0;
        l1 = l1 * sc1 + ls1;
        #pragma unroll
        for (int f = 0; f < 16; f++) {
            o[f][0] *= sc0; o[f][1] *= sc0;
            o[f][2] *= sc1; o[f][3] *= sc1;
        }

        // ---- store P (tf32) to own rows; pad 72 -> conflict-free STS.64 ----
        #pragma unroll
        for (int nf = 0; nf < 8; nf++) {
            float2 p0 = make_float2(tf32r(s[nf][0]), tf32r(s[nf][1]));
            float2 p1 = make_float2(tf32r(s[nf][2]), tf32r(s[nf][3]));
            *(float2*)&Ps[(wr + g    ) * 72 + nf * 8 + 2 * tg] = p0;
            *(float2*)&Ps[(wr + g + 8) * 72 + nf * 8 + 2 * tg] = p1;
        }
        __syncwarp();

        // ---- O += P V (k over 64 keys, n over 128 d-cols) ----
        #pragma unroll
        for (int ks = 0; ks < 8; ks++) {
            const int kk = ks * 8;
            uint32_t a0 = __float_as_uint(Ps[(wr + g    ) * 72 + kk + tg]);
            uint32_t a1 = __float_as_uint(Ps[(wr + g + 8) * 72 + kk + tg]);
            uint32_t a2 = __float_as_uint(Ps[(wr + g    ) * 72 + kk + tg + 4]);
            uint32_t a3 = __float_as_uint(Ps[(wr + g + 8) * 72 + kk + tg + 4]);
            #pragma unroll
            for (int nf = 0; nf < 16; nf++) {
                uint32_t b0 = __float_as_uint(Vs[(kk + tg    ) * 136 + nf * 8 + g]);
                uint32_t b1 = __float_as_uint(Vs[(kk + tg + 4) * 136 + nf * 8 + g]);
                mma_tf32(o[nf], a0, a1, a2, a3, b0, b1);
            }
        }
    }

    // ---- epilogue: out = q + O / l ----
    l0 = quadSum(l0); l1 = quadSum(l1);
    const float i0 = 1.f / l0, i1 = 1.f / l1;
    const int r0 = wr + g, r1 = wr + g + 8;
    #pragma unroll
    for (int nf = 0; nf < 16; nf++) {
        int c = nf * 8 + 2 * tg;
        const float2 q0 = *(const float2*)(qp + (long)r0 * DMODEL + c);
        const float2 q1 = *(const float2*)(qp + (long)r1 * DMODEL + c);
        float2 w0 = make_float2(q0.x + o[nf][0] * i0, q0.y + o[nf][1] * i0);
        float2 w1 = make_float2(q1.x + o[nf][2] * i1, q1.y + o[nf][3] * i1);
        *(float2*)(op + (long)r0 * DMODEL + c) = w0;
        *(float2*)(op + (long)r1 * DMODEL + c) = w1;
    }
}

// ---------------------------------------------------------------------------
// LayerNorm over rows of width 1024.
// ---------------------------------------------------------------------------
__global__ __launch_bounds__(256)
void ln_kernel(const float* __restrict__ X, float* __restrict__ Y,
               const float* __restrict__ gam, const float* __restrict__ bet)
{
    const float* x = X + (size_t)blockIdx.x * DMODEL;
    float*       y = Y + (size_t)blockIdx.x * DMODEL;
    const int tid = threadIdx.x;
    float v[4];
    float s = 0.f, sq = 0.f;
    #pragma unroll
    for (int i = 0; i < 4; i++) {
        v[i] = x[i * 256 + tid];
        s  += v[i];
        sq += v[i] * v[i];
    }
    s  = warpSum(s);
    sq = warpSum(sq);
    __shared__ float a1[8], a2[8];
    if ((tid & 31) == 0) { a1[tid >> 5] = s; a2[tid >> 5] = sq; }
    __syncthreads();
    float S1 = ((a1[0] + a1[1]) + (a1[2] + a1[3])) + ((a1[4] + a1[5]) + (a1[6] + a1[7]));
    float S2 = ((a2[0] + a2[1]) + (a2[2] + a2[3])) + ((a2[4] + a2[5]) + (a2[6] + a2[7]));
    const float invn = 1.f / (float)DMODEL;
    float mu  = S1 * invn;
    float var = S2 * invn - mu * mu;
    float rs  = rsqrtf(var + 1e-5f);
    #pragma unroll
    for (int i = 0; i < 4; i++) {
        int c = i * 256 + tid;
        y[c] = (v[i] - mu) * rs * gam[c] + bet[c];
    }
}

// ---------------------------------------------------------------------------
// launch
// ---------------------------------------------------------------------------
extern "C" void kernel_launch(void* const* d_in, const int* in_sizes, int n_in,
                              void* d_out, int out_size)
{
    (void)in_sizes; (void)n_in; (void)out_size;
    const float* Q  = (const float*)d_in[0];
    const float* K_ = (const float*)d_in[1];
    const float* Wq = (const float*)d_in[2];
    const float* bq = (const float*)d_in[3];
    const float* Wk = (const float*)d_in[4];
    const float* bk = (const float*)d_in[5];
    const float* Wv = (const float*)d_in[6];
    const float* bv = (const float*)d_in[7];
    const float* Wo = (const float*)d_in[8];
    const float* bo = (const float*)d_in[9];
    const float* g0 = (const float*)d_in[10];
    const float* b0 = (const float*)d_in[11];
    const float* g1 = (const float*)d_in[12];
    const float* b1 = (const float*)d_in[13];
    float* out = (float*)d_out;

    float *qb, *kb, *vb, *att, *x0;
    cudaGetSymbolAddress((void**)&qb,  g_qb);
    cudaGetSymbolAddress((void**)&kb,  g_kb);
    cudaGetSymbolAddress((void**)&vb,  g_vb);
    cudaGetSymbolAddress((void**)&att, g_att);
    cudaGetSymbolAddress((void**)&x0,  g_x0);

    const int GEMM_SMEM  = 2 * 2 * 128 * 36 * 4;   // 73728
    const int FLASH_SMEM = (128*132 + 64*132 + 64*136 + 128*72) * 4;  // 173056
    cudaFuncSetAttribute(gemm_nt<0>,  cudaFuncAttributeMaxDynamicSharedMemorySize, GEMM_SMEM);
    cudaFuncSetAttribute(gemm_nt<3>,  cudaFuncAttributeMaxDynamicSharedMemorySize, GEMM_SMEM);
    cudaFuncSetAttribute(flash_kernel, cudaFuncAttributeMaxDynamicSharedMemorySize, FLASH_SMEM);

    dim3 blk(256);
    dim3 gp(DMODEL / 128, NROWS / 128);          // (8, 64)

    gemm_nt<0><<<gp, blk, GEMM_SMEM>>>(Q,  Wq, qb, bq, nullptr);
    gemm_nt<0><<<gp, blk, GEMM_SMEM>>>(K_, Wk, kb, bk, nullptr);
    gemm_nt<0><<<gp, blk, GEMM_SMEM>>>(K_, Wv, vb, bv, nullptr);

    dim3 gf(NKEYS / 128, NBH);                   // (16, 32)
    flash_kernel<<<gf, blk, FLASH_SMEM>>>(qb, kb, vb, att);

    ln_kernel<<<NROWS, 256>>>(att, x0, g0, b0);

    gemm_nt<3><<<gp, blk, GEMM_SMEM>>>(x0, Wo, att, bo, x0);

    ln_kernel<<<NROWS, 256>>>(att, out, g1, b1);
}

// round 4
// speedup vs baseline: 1.5475x; 1.0010x over previous
#include <cuda_runtime.h>
#include <cstdint>

// ---------------------------------------------------------------------------
// B=4, NQ=NK=2048, D=1024, H=8, d=128
// ---------------------------------------------------------------------------
#define NROWS   8192
#define DMODEL  1024
#define NKEYS   2048
#define NBH     32

__device__ float g_qb [NROWS * DMODEL];
__device__ float g_kb [NROWS * DMODEL];
__device__ float g_vb [NROWS * DMODEL];
__device__ float g_att[NROWS * DMODEL];
__device__ float g_x0 [NROWS * DMODEL];

// ---------------------------------------------------------------------------
// helpers
// ---------------------------------------------------------------------------
__device__ __forceinline__ float tf32r(float x) {
    uint32_t u;
    asm("cvt.rna.tf32.f32 %0, %1;" : "=r"(u) : "f"(x));
    return __uint_as_float(u);
}
__device__ __forceinline__ uint32_t tf32u(float x) {
    uint32_t u;
    asm("cvt.rna.tf32.f32 %0, %1;" : "=r"(u) : "f"(x));
    return u;
}
__device__ __forceinline__ void mma_tf32(float* c, uint32_t a0, uint32_t a1,
                                         uint32_t a2, uint32_t a3,
                                         uint32_t b0, uint32_t b1) {
    asm volatile(
        "mma.sync.aligned.m16n8k8.row.col.f32.tf32.tf32.f32 "
        "{%0,%1,%2,%3}, {%4,%5,%6,%7}, {%8,%9}, {%0,%1,%2,%3};"
        : "+f"(c[0]), "+f"(c[1]), "+f"(c[2]), "+f"(c[3])
        : "r"(a0), "r"(a1), "r"(a2), "r"(a3), "r"(b0), "r"(b1));
}
__device__ __forceinline__ void cp16(void* dst, const void* src) {
    uint32_t d = (uint32_t)__cvta_generic_to_shared(dst);
    asm volatile("cp.async.ca.shared.global [%0], [%1], 16;\n" :: "r"(d), "l"(src));
}
#define CP_COMMIT() asm volatile("cp.async.commit_group;\n")
#define CP_WAIT1()  asm volatile("cp.async.wait_group 1;\n")

__device__ __forceinline__ float warpSum(float v) {
    #pragma unroll
    for (int o = 16; o; o >>= 1) v += __shfl_xor_sync(0xFFFFFFFFu, v, o);
    return v;
}
__device__ __forceinline__ float quadMax(float v) {
    v = fmaxf(v, __shfl_xor_sync(0xFFFFFFFFu, v, 1));
    v = fmaxf(v, __shfl_xor_sync(0xFFFFFFFFu, v, 2));
    return v;
}
__device__ __forceinline__ float quadSum(float v) {
    v += __shfl_xor_sync(0xFFFFFFFFu, v, 1);
    v += __shfl_xor_sync(0xFFFFFFFFu, v, 2);
    return v;
}

// ---------------------------------------------------------------------------
// GEMM: C[8192,1024] = epi( A[8192,1024] @ B^T ), B[1024,1024] row-major n,k.
// cp.async 2-stage double buffer. Both tiles in [row][36] layout (bank-clean:
// stage banks = 4*lane, frag banks = 4g+tg, both bijective mod 32).
// EPI 0: +bias ; EPI 3: Res + relu(acc + bias)
// ---------------------------------------------------------------------------
template<int EPI>
__global__ __launch_bounds__(256, 2)
void gemm_nt(const float* __restrict__ A, const float* __restrict__ B,
             float* __restrict__ C,
             const float* __restrict__ bias, const float* __restrict__ Res)
{
    extern __shared__ float sm[];
    float* As = sm;              // [2][128][36]
    float* Bs = sm + 2 * 128 * 36;
    #define ASM(s,r,c) As[(s)*4608 + (r)*36 + (c)]
    #define BSM(s,r,c) Bs[(s)*4608 + (r)*36 + (c)]

    const int m0 = blockIdx.y * 128, n0 = blockIdx.x * 128;
    const int tid = threadIdx.x;
    const int warp = tid >> 5, lane = tid & 31;
    const int wm = (warp >> 2) * 64, wn = (warp & 3) * 32;
    const int g = lane >> 2, tg = lane & 3;
    const int sr = tid >> 3, skq = (tid & 7) << 2;

    float acc[4][4][4];
    #pragma unroll
    for (int i = 0; i < 4; i++)
        #pragma unroll
        for (int j = 0; j < 4; j++)
            #pragma unroll
            for (int e = 0; e < 4; e++) acc[i][j][e] = 0.f;

    auto stage = [&](int s, int k0) {
        #pragma unroll
        for (int i = 0; i < 4; i++) {
            int r = sr + 32 * i;
            cp16(&ASM(s, r, skq), A + (long)(m0 + r) * DMODEL + k0 + skq);
            cp16(&BSM(s, r, skq), B + (long)(n0 + r) * DMODEL + k0 + skq);
        }
    };

    stage(0, 0);  CP_COMMIT();
    stage(1, 32); CP_COMMIT();

    for (int kt = 0; kt < 32; kt++) {
        CP_WAIT1();
        __syncthreads();
        const int s = kt & 1;
        #pragma unroll
        for (int ks = 0; ks < 4; ks++) {
            const int kk = ks * 8;
            uint32_t af[4][4], bf[4][2];
            #pragma unroll
            for (int mf = 0; mf < 4; mf++) {
                int r = wm + mf * 16 + g;
                af[mf][0] = tf32u(ASM(s, r,     kk + tg));
                af[mf][1] = tf32u(ASM(s, r + 8, kk + tg));
                af[mf][2] = tf32u(ASM(s, r,     kk + tg + 4));
                af[mf][3] = tf32u(ASM(s, r + 8, kk + tg + 4));
            }
            #pragma unroll
            for (int nf = 0; nf < 4; nf++) {
                int c = wn + nf * 8 + g;
                bf[nf][0] = tf32u(BSM(s, c, kk + tg));
                bf[nf][1] = tf32u(BSM(s, c, kk + tg + 4));
            }
            #pragma unroll
            for (int mf = 0; mf < 4; mf++)
                #pragma unroll
                for (int nf = 0; nf < 4; nf++)
                    mma_tf32(acc[mf][nf], af[mf][0], af[mf][1], af[mf][2], af[mf][3],
                             bf[nf][0], bf[nf][1]);
        }
        __syncthreads();
        if (kt < 30) stage(s, (kt + 2) * 32);
        CP_COMMIT();   // commit every iter (empty groups keep wait_group numbering)
    }

    #pragma unroll
    for (int mf = 0; mf < 4; mf++) {
        #pragma unroll
        for (int nf = 0; nf < 4; nf++) {
            int r = m0 + wm + mf * 16 + g;
            int c = n0 + wn + nf * 8 + 2 * tg;
            #pragma unroll
            for (int e = 0; e < 4; e++) {
                int rr = r + (e >> 1) * 8;
                int cc = c + (e & 1);
                float v = acc[mf][nf][e];
                if (EPI == 0) { v += bias[cc]; }
                else          { v += bias[cc]; v = fmaxf(v, 0.f);
                                v += Res[(long)rr * DMODEL + cc]; }
                C[(long)rr * DMODEL + cc] = v;
            }
        }
    }
    #undef ASM
    #undef BSM
}

// ---------------------------------------------------------------------------
// Flash attention: per CTA one (b,h) and 128 q-rows; loop 32 tiles of 64 keys.
// 8 warps; each warp owns 16 full rows -> softmax stats stay in registers.
// out = q + softmax(q k^T / sqrt(d)) v   (residual q read exactly from gmem)
// smem: Qs[128][132] | Ks[64][132] | Vs[64][136] | Ps[128][72]  = 173056 B
// ---------------------------------------------------------------------------
__global__ __launch_bounds__(256, 1)
void flash_kernel(const float* __restrict__ qb, const float* __restrict__ kb,
                  const float* __restrict__ vb, float* __restrict__ att)
{
    extern __shared__ float sm[];
    float* Qs = sm;                      // 128*132
    float* Ks = Qs + 128 * 132;          // 64*132
    float* Vs = Ks + 64 * 132;           // 64*136
    float* Ps = Vs + 64 * 136;           // 128*72

    const int bh = blockIdx.y, zb = bh >> 3, zh = bh & 7;
    const long base = (long)zb * (NKEYS * DMODEL) + zh * 128;
    const float* qp = qb + base + (long)blockIdx.x * 128 * DMODEL;
    const float* kp = kb + base;
    const float* vp = vb + base;
    float*       op = att + base + (long)blockIdx.x * 128 * DMODEL;

    const int tid = threadIdx.x, warp = tid >> 5, lane = tid & 31;
    const int g = lane >> 2, tg = lane & 3;
    const int wr = warp * 16;
    const float isq = 0.088388347648318447f;   // 1/sqrt(128)

    // load Q tile (tf32)
    #pragma unroll
    for (int i = 0; i < 16; i++) {
        int idx = tid + i * 256;
        int r = idx >> 5, cq = (idx & 31) << 2;
        float4 v = *(const float4*)(qp + (long)r * DMODEL + cq);
        Qs[r * 132 + cq + 0] = tf32r(v.x);
        Qs[r * 132 + cq + 1] = tf32r(v.y);
        Qs[r * 132 + cq + 2] = tf32r(v.z);
        Qs[r * 132 + cq + 3] = tf32r(v.w);
    }

    float o[16][4];
    #pragma unroll
    for (int f = 0; f < 16; f++)
        #pragma unroll
        for (int e = 0; e < 4; e++) o[f][e] = 0.f;
    float mrow0 = -1e30f, mrow1 = -1e30f, l0 = 0.f, l1 = 0.f;

    for (int j = 0; j < 32; j++) {
        __syncthreads();                       // prev iter done reading Ks/Vs
        #pragma unroll
        for (int i = 0; i < 8; i++) {
            int idx = tid + i * 256;
            int r = idx >> 5, cq = (idx & 31) << 2;
            const long gro = (long)(j * 64 + r) * DMODEL + cq;
            float4 kv = *(const float4*)(kp + gro);
            Ks[r * 132 + cq + 0] = tf32r(kv.x);
            Ks[r * 132 + cq + 1] = tf32r(kv.y);
            Ks[r * 132 + cq + 2] = tf32r(kv.z);
            Ks[r * 132 + cq + 3] = tf32r(kv.w);
            float4 vv = *(const float4*)(vp + gro);
            Vs[r * 136 + cq + 0] = tf32r(vv.x);
            Vs[r * 136 + cq + 1] = tf32r(vv.y);
            Vs[r * 136 + cq + 2] = tf32r(vv.z);
            Vs[r * 136 + cq + 3] = tf32r(vv.w);
        }
        __syncthreads();

        // ---- S = Q K^T (warp: 16 rows x 64 keys) ----
        float s[8][4];
        #pragma unroll
        for (int nf = 0; nf < 8; nf++)
            #pragma unroll
            for (int e = 0; e < 4; e++) s[nf][e] = 0.f;
        #pragma unroll
        for (int ks = 0; ks < 16; ks++) {
            const int kk = ks * 8;
            uint32_t a0 = __float_as_uint(Qs[(wr + g    ) * 132 + kk + tg]);
            uint32_t a1 = __float_as_uint(Qs[(wr + g + 8) * 132 + kk + tg]);
            uint32_t a2 = __float_as_uint(Qs[(wr + g    ) * 132 + kk + tg + 4]);
            uint32_t a3 = __float_as_uint(Qs[(wr + g + 8) * 132 + kk + tg + 4]);
            #pragma unroll
            for (int nf = 0; nf < 8; nf++) {
                uint32_t b0 = __float_as_uint(Ks[(nf * 8 + g) * 132 + kk + tg]);
                uint32_t b1 = __float_as_uint(Ks[(nf * 8 + g) * 132 + kk + tg + 4]);
                mma_tf32(s[nf], a0, a1, a2, a3, b0, b1);
            }
        }

        // ---- online softmax (rows g and g+8 of this warp) ----
        float tm0 = -1e30f, tm1 = -1e30f;
        #pragma unroll
        for (int nf = 0; nf < 8; nf++) {
            s[nf][0] *= isq; s[nf][1] *= isq; s[nf][2] *= isq; s[nf][3] *= isq;
            tm0 = fmaxf(tm0, fmaxf(s[nf][0], s[nf][1]));
            tm1 = fmaxf(tm1, fmaxf(s[nf][2], s[nf][3]));
        }
        tm0 = quadMax(tm0); tm1 = quadMax(tm1);
        float mn0 = fmaxf(mrow0, tm0), mn1 = fmaxf(mrow1, tm1);
        float sc0 = __expf(mrow0 - mn0), sc1 = __expf(mrow1 - mn1);
        mrow0 = mn0; mrow1 = mn1;
        float ls0 = 0.f, ls1 = 0.f;
        #pragma unroll
        for (int nf = 0; nf < 8; nf++) {
            s[nf][0] = __expf(s[nf][0] - mn0);
            s[nf][1] = __expf(s[nf][1] - mn0);
            s[nf][2] = __expf(s[nf][2] - mn1);
            s[nf][3] = __expf(s[nf][3] - mn1);
            ls0 += s[nf][0] + s[nf][1];
            ls1 += s[nf][2] + s[nf][3];
        }
        l0 = l0 * sc0 + ls0;
        l1 = l1 * sc1 + ls1;
        #pragma unroll
        for (int f = 0; f < 16; f++) {
            o[f][0] *= sc0; o[f][1] *= sc0;
            o[f][2] *= sc1; o[f][3] *= sc1;
        }

        // ---- store P (tf32) to own rows; pad 72 -> conflict-free STS.64 ----
        #pragma unroll
        for (int nf = 0; nf < 8; nf++) {
            float2 p0 = make_float2(tf32r(s[nf][0]), tf32r(s[nf][1]));
            float2 p1 = make_float2(tf32r(s[nf][2]), tf32r(s[nf][3]));
            *(float2*)&Ps[(wr + g    ) * 72 + nf * 8 + 2 * tg] = p0;
            *(float2*)&Ps[(wr + g + 8) * 72 + nf * 8 + 2 * tg] = p1;
        }
        __syncwarp();

        // ---- O += P V (k over 64 keys, n over 128 d-cols) ----
        #pragma unroll
        for (int ks = 0; ks < 8; ks++) {
            const int kk = ks * 8;
            uint32_t a0 = __float_as_uint(Ps[(wr + g    ) * 72 + kk + tg]);
            uint32_t a1 = __float_as_uint(Ps[(wr + g + 8) * 72 + kk + tg]);
            uint32_t a2 = __float_as_uint(Ps[(wr + g    ) * 72 + kk + tg + 4]);
            uint32_t a3 = __float_as_uint(Ps[(wr + g + 8) * 72 + kk + tg + 4]);
            #pragma unroll
            for (int nf = 0; nf < 16; nf++) {
                uint32_t b0 = __float_as_uint(Vs[(kk + tg    ) * 136 + nf * 8 + g]);
                uint32_t b1 = __float_as_uint(Vs[(kk + tg + 4) * 136 + nf * 8 + g]);
                mma_tf32(o[nf], a0, a1, a2, a3, b0, b1);
            }
        }
    }

    // ---- epilogue: out = q + O / l ----
    l0 = quadSum(l0); l1 = quadSum(l1);
    const float i0 = 1.f / l0, i1 = 1.f / l1;
    const int r0 = wr + g, r1 = wr + g + 8;
    #pragma unroll
    for (int nf = 0; nf < 16; nf++) {
        int c = nf * 8 + 2 * tg;
        const float2 q0 = *(const float2*)(qp + (long)r0 * DMODEL + c);
        const float2 q1 = *(const float2*)(qp + (long)r1 * DMODEL + c);
        float2 w0 = make_float2(q0.x + o[nf][0] * i0, q0.y + o[nf][1] * i0);
        float2 w1 = make_float2(q1.x + o[nf][2] * i1, q1.y + o[nf][3] * i1);
        *(float2*)(op + (long)r0 * DMODEL + c) = w0;
        *(float2*)(op + (long)r1 * DMODEL + c) = w1;
    }
}

// ---------------------------------------------------------------------------
// LayerNorm over rows of width 1024.
// ---------------------------------------------------------------------------
__global__ __launch_bounds__(256)
void ln_kernel(const float* __restrict__ X, float* __restrict__ Y,
               const float* __restrict__ gam, const float* __restrict__ bet)
{
    const float* x = X + (size_t)blockIdx.x * DMODEL;
    float*       y = Y + (size_t)blockIdx.x * DMODEL;
    const int tid = threadIdx.x;
    float v[4];
    float s = 0.f, sq = 0.f;
    #pragma unroll
    for (int i = 0; i < 4; i++) {
        v[i] = x[i * 256 + tid];
        s  += v[i];
        sq += v[i] * v[i];
    }
    s  = warpSum(s);
    sq = warpSum(sq);
    __shared__ float a1[8], a2[8];
    if ((tid & 31) == 0) { a1[tid >> 5] = s; a2[tid >> 5] = sq; }
    __syncthreads();
    float S1 = ((a1[0] + a1[1]) + (a1[2] + a1[3])) + ((a1[4] + a1[5]) + (a1[6] + a1[7]));
    float S2 = ((a2[0] + a2[1]) + (a2[2] + a2[3])) + ((a2[4] + a2[5]) + (a2[6] + a2[7]));
    const float invn = 1.f / (float)DMODEL;
    float mu  = S1 * invn;
    float var = S2 * invn - mu * mu;
    float rs  = rsqrtf(var + 1e-5f);
    #pragma unroll
    for (int i = 0; i < 4; i++) {
        int c = i * 256 + tid;
        y[c] = (v[i] - mu) * rs * gam[c] + bet[c];
    }
}

// ---------------------------------------------------------------------------
// launch
// ---------------------------------------------------------------------------
extern "C" void kernel_launch(void* const* d_in, const int* in_sizes, int n_in,
                              void* d_out, int out_size)
{
    (void)in_sizes; (void)n_in; (void)out_size;
    const float* Q  = (const float*)d_in[0];
    const float* K_ = (const float*)d_in[1];
    const float* Wq = (const float*)d_in[2];
    const float* bq = (const float*)d_in[3];
    const float* Wk = (const float*)d_in[4];
    const float* bk = (const float*)d_in[5];
    const float* Wv = (const float*)d_in[6];
    const float* bv = (const float*)d_in[7];
    const float* Wo = (const float*)d_in[8];
    const float* bo = (const float*)d_in[9];
    const float* g0 = (const float*)d_in[10];
    const float* b0 = (const float*)d_in[11];
    const float* g1 = (const float*)d_in[12];
    const float* b1 = (const float*)d_in[13];
    float* out = (float*)d_out;

    float *qb, *kb, *vb, *att, *x0;
    cudaGetSymbolAddress((void**)&qb,  g_qb);
    cudaGetSymbolAddress((void**)&kb,  g_kb);
    cudaGetSymbolAddress((void**)&vb,  g_vb);
    cudaGetSymbolAddress((void**)&att, g_att);
    cudaGetSymbolAddress((void**)&x0,  g_x0);

    const int GEMM_SMEM  = 2 * 2 * 128 * 36 * 4;   // 73728
    const int FLASH_SMEM = (128*132 + 64*132 + 64*136 + 128*72) * 4;  // 173056
    cudaFuncSetAttribute(gemm_nt<0>,  cudaFuncAttributeMaxDynamicSharedMemorySize, GEMM_SMEM);
    cudaFuncSetAttribute(gemm_nt<3>,  cudaFuncAttributeMaxDynamicSharedMemorySize, GEMM_SMEM);
    cudaFuncSetAttribute(flash_kernel, cudaFuncAttributeMaxDynamicSharedMemorySize, FLASH_SMEM);

    dim3 blk(256);
    dim3 gp(DMODEL / 128, NROWS / 128);          // (8, 64)

    gemm_nt<0><<<gp, blk, GEMM_SMEM>>>(Q,  Wq, qb, bq, nullptr);
    gemm_nt<0><<<gp, blk, GEMM_SMEM>>>(K_, Wk, kb, bk, nullptr);
    gemm_nt<0><<<gp, blk, GEMM_SMEM>>>(K_, Wv, vb, bv, nullptr);

    dim3 gf(NKEYS / 128, NBH);                   // (16, 32)
    flash_kernel<<<gf, blk, FLASH_SMEM>>>(qb, kb, vb, att);

    ln_kernel<<<NROWS, 256>>>(att, x0, g0, b0);

    gemm_nt<3><<<gp, blk, GEMM_SMEM>>>(x0, Wo, att, bo, x0);

    ln_kernel<<<NROWS, 256>>>(att, out, g1, b1);
}

// round 6
// speedup vs baseline: 3.2560x; 2.1040x over previous
#include <cuda_runtime.h>
#include <cuda_fp16.h>
#include <cstdint>

#define NROWS   8192
#define DMODEL  1024
#define NKEYS   2048
#define NBH     32

__device__ __half g_Qh [NROWS * DMODEL];
__device__ __half g_Kh [NROWS * DMODEL];
__device__ __half g_Wqh[DMODEL * DMODEL];
__device__ __half g_Wkh[DMODEL * DMODEL];
__device__ __half g_Wvh[DMODEL * DMODEL];
__device__ __half g_Woh[DMODEL * DMODEL];
__device__ __half g_qh [NROWS * DMODEL];
__device__ __half g_kh [NROWS * DMODEL];
__device__ __half g_vh [NROWS * DMODEL];
__device__ __half g_x0h[NROWS * DMODEL];
__device__ float  g_att[NROWS * DMODEL];
__device__ float  g_x0f[NROWS * DMODEL];

__device__ __forceinline__ uint32_t h2u(__half2 h) {
    uint32_t u;
    asm("mov.b32 %0, %1;" : "=r"(u) : "r"(*(uint32_t*)&h));
    return u;
}
__device__ __forceinline__ void ldsm4(uint32_t a[4], uint32_t addr) {
    asm volatile("ldmatrix.sync.aligned.m8n8.x4.shared.b16 {%0,%1,%2,%3}, [%4];"
                 : "=r"(a[0]), "=r"(a[1]), "=r"(a[2]), "=r"(a[3]) : "r"(addr));
}
__device__ __forceinline__ void ldsm4t(uint32_t a[4], uint32_t addr) {
    asm volatile("ldmatrix.sync.aligned.m8n8.x4.trans.shared.b16 {%0,%1,%2,%3}, [%4];"
                 : "=r"(a[0]), "=r"(a[1]), "=r"(a[2]), "=r"(a[3]) : "r"(addr));
}
__device__ __forceinline__ void mma_h(float* c, const uint32_t a[4], uint32_t b0, uint32_t b1) {
    asm volatile("mma.sync.aligned.m16n8k16.row.col.f32.f16.f16.f32 "
                 "{%0,%1,%2,%3}, {%4,%5,%6,%7}, {%8,%9}, {%0,%1,%2,%3};"
                 : "+f"(c[0]), "+f"(c[1]), "+f"(c[2]), "+f"(c[3])
                 : "r"(a[0]), "r"(a[1]), "r"(a[2]), "r"(a[3]), "r"(b0), "r"(b1));
}
__device__ __forceinline__ void cp16(uint32_t dst, const void* src) {
    asm volatile("cp.async.ca.shared.global [%0], [%1], 16;\n" :: "r"(dst), "l"(src));
}
#define CP_COMMIT() asm volatile("cp.async.commit_group;\n")
#define CP_WAIT1()  asm volatile("cp.async.wait_group 1;\n")

__device__ __forceinline__ float warpSum(float v) {
    #pragma unroll
    for (int o = 16; o; o >>= 1) v += __shfl_xor_sync(0xFFFFFFFFu, v, o);
    return v;
}
__device__ __forceinline__ float quadMax(float v) {
    v = fmaxf(v, __shfl_xor_sync(0xFFFFFFFFu, v, 1));
    v = fmaxf(v, __shfl_xor_sync(0xFFFFFFFFu, v, 2));
    return v;
}
__device__ __forceinline__ float quadSum(float v) {
    v += __shfl_xor_sync(0xFFFFFFFFu, v, 1);
    v += __shfl_xor_sync(0xFFFFFFFFu, v, 2);
    return v;
}

// ---------------- fp32 -> fp16 ----------------
__global__ __launch_bounds__(256)
void conv_f2h(const float* __restrict__ s, __half* __restrict__ d, int n)
{
    int i = (blockIdx.x * 256 + threadIdx.x) * 4;
    if (i < n) {
        float4 v = *(const float4*)(s + i);
        __half2* o = (__half2*)(d + i);
        o[0] = __floats2half2_rn(v.x, v.y);
        o[1] = __floats2half2_rn(v.z, v.w);
    }
}

// ---------------------------------------------------------------------------
// fp16 GEMM C = epi(A @ B^T). A[8192,1024]h, B[1024,1024]h (n,k row-major).
// BM=128 BN=128 BK=64, 8 warps (2x4) each 64x32. XOR-swizzled, cp.async x2.
// EPI 0: half C = acc + bias.  EPI 3: float C = Res + relu(acc + bias).
// ---------------------------------------------------------------------------
template<int EPI>
__global__ __launch_bounds__(256, 2)
void gemm_h(const __half* __restrict__ A, const __half* __restrict__ B,
            void* __restrict__ Cv, const float* __restrict__ bias,
            const float* __restrict__ Res)
{
    extern __shared__ char smc[];
    const uint32_t smA = (uint32_t)__cvta_generic_to_shared(smc);
    const uint32_t smB = smA + 32768;

    const int m0 = blockIdx.y * 128, n0 = blockIdx.x * 128;
    const int tid = threadIdx.x, warp = tid >> 5, lane = tid & 31;
    const int wm = (warp >> 2) * 64, wn = (warp & 3) * 32;
    const int g = lane >> 2, tg = lane & 3;
    const uint32_t l7 = lane & 7, lb3 = (lane >> 3) & 1, lb4 = (uint32_t)lane >> 4;

    float acc[4][4][4];
    #pragma unroll
    for (int i = 0; i < 4; i++)
        #pragma unroll
        for (int j = 0; j < 4; j++)
            #pragma unroll
            for (int e = 0; e < 4; e++) acc[i][j][e] = 0.f;

    auto stage = [&](int s, int k0) {
        #pragma unroll
        for (int i = 0; i < 4; i++) {
            int idx = tid + i * 256;
            uint32_t row = idx >> 3, c = idx & 7;
            uint32_t d = s * 16384 + row * 128 + ((c ^ (row & 7)) * 16);
            cp16(smA + d, A + (long)(m0 + row) * DMODEL + k0 + c * 8);
            cp16(smB + d, B + (long)(n0 + row) * DMODEL + k0 + c * 8);
        }
    };
    stage(0, 0);  CP_COMMIT();
    stage(1, 64); CP_COMMIT();

    for (int kt = 0; kt < 16; kt++) {
        CP_WAIT1();
        __syncthreads();
        const uint32_t sa = smA + (kt & 1) * 16384;
        const uint32_t sb = smB + (kt & 1) * 16384;
        #pragma unroll
        for (int ks = 0; ks < 4; ks++) {
            uint32_t af[4][4], bf[2][4];
            #pragma unroll
            for (int mi = 0; mi < 4; mi++) {
                uint32_t row = wm + mi * 16 + lb3 * 8 + l7;
                uint32_t cc  = ks * 2 + lb4;
                ldsm4(af[mi], sa + row * 128 + ((cc ^ (row & 7)) * 16));
            }
            #pragma unroll
            for (int nj = 0; nj < 2; nj++) {
                uint32_t row = wn + nj * 16 + lb4 * 8 + l7;
                uint32_t cc  = ks * 2 + lb3;
                ldsm4(bf[nj], sb + row * 128 + ((cc ^ (row & 7)) * 16));
            }
            #pragma unroll
            for (int mi = 0; mi < 4; mi++)
                #pragma unroll
                for (int nf = 0; nf < 4; nf++)
                    mma_h(acc[mi][nf], af[mi], bf[nf >> 1][(nf & 1) * 2],
                          bf[nf >> 1][(nf & 1) * 2 + 1]);
        }
        __syncthreads();
        if (kt < 14) stage(kt & 1, (kt + 2) * 64);
        CP_COMMIT();
    }

    #pragma unroll
    for (int mi = 0; mi < 4; mi++) {
        #pragma unroll
        for (int nf = 0; nf < 4; nf++) {
            int r = m0 + wm + mi * 16 + g;
            int c = n0 + wn + nf * 8 + 2 * tg;
            float b0 = bias[c], b1 = bias[c + 1];
            if (EPI == 0) {
                __half* C = (__half*)Cv;
                *(__half2*)(C + (long)r * DMODEL + c) =
                    __floats2half2_rn(acc[mi][nf][0] + b0, acc[mi][nf][1] + b1);
                *(__half2*)(C + (long)(r + 8) * DMODEL + c) =
                    __floats2half2_rn(acc[mi][nf][2] + b0, acc[mi][nf][3] + b1);
            } else {
                float* C = (float*)Cv;
                float2 v0, v1;
                v0.x = fmaxf(acc[mi][nf][0] + b0, 0.f) + Res[(long)r * DMODEL + c];
                v0.y = fmaxf(acc[mi][nf][1] + b1, 0.f) + Res[(long)r * DMODEL + c + 1];
                v1.x = fmaxf(acc[mi][nf][2] + b0, 0.f) + Res[(long)(r + 8) * DMODEL + c];
                v1.y = fmaxf(acc[mi][nf][3] + b1, 0.f) + Res[(long)(r + 8) * DMODEL + c + 1];
                *(float2*)(C + (long)r * DMODEL + c) = v0;
                *(float2*)(C + (long)(r + 8) * DMODEL + c) = v1;
            }
        }
    }
}

// ---------------------------------------------------------------------------
// fp16 flash: CTA = one (b,h), 128 q-rows; 32 tiles of 64 keys, K/V cp.async
// double-buffered. Warp owns 16 rows. P stays in registers (FA2 layout trick).
// smem halves, row stride 136 (=272B, ldsm conflict-free).
// Q:[0,34816) Kbuf2:[34816,69632) Vbuf2:[69632,104448)
// ---------------------------------------------------------------------------
__global__ __launch_bounds__(256, 1)
void flash_h(const __half* __restrict__ qb, const __half* __restrict__ kb,
             const __half* __restrict__ vb, float* __restrict__ att)
{
    extern __shared__ char smc[];
    const uint32_t smQ = (uint32_t)__cvta_generic_to_shared(smc);
    const uint32_t smK = smQ + 34816;
    const uint32_t smV = smQ + 69632;

    const int bh = blockIdx.y, zb = bh >> 3, zh = bh & 7;
    const long base = (long)zb * (NKEYS * DMODEL) + zh * 128;
    const __half* qp = qb + base + (long)blockIdx.x * 128 * DMODEL;
    const __half* kp = kb + base;
    const __half* vp = vb + base;
    float*        op = att + base + (long)blockIdx.x * 128 * DMODEL;

    const int tid = threadIdx.x, warp = tid >> 5, lane = tid & 31;
    const int g = lane >> 2, tg = lane & 3;
    const int wr = warp * 16;
    const uint32_t l7 = lane & 7, lb3 = (lane >> 3) & 1, lb4 = (uint32_t)lane >> 4;
    const float isq = 0.088388347648318447f;

    // stage Q: 128 rows x 16 chunks of 16B
    #pragma unroll
    for (int i = 0; i < 8; i++) {
        int idx = tid + i * 256;
        uint32_t r = idx >> 4, c = idx & 15;
        cp16(smQ + r * 272 + c * 16, qp + (long)r * DMODEL + c * 8);
    }
    auto stage = [&](int s, int jt) {
        #pragma unroll
        for (int i = 0; i < 4; i++) {
            int idx = tid + i * 256;
            uint32_t r = idx >> 4, c = idx & 15;
            const long go = (long)(jt * 64 + r) * DMODEL + c * 8;
            uint32_t d = s * 17408 + r * 272 + c * 16;
            cp16(smK + d, kp + go);
            cp16(smV + d, vp + go);
        }
    };
    stage(0, 0); CP_COMMIT();
    stage(1, 1); CP_COMMIT();

    float o[16][4];
    #pragma unroll
    for (int f = 0; f < 16; f++)
        #pragma unroll
        for (int e = 0; e < 4; e++) o[f][e] = 0.f;
    float m0 = -1e30f, m1 = -1e30f, l0 = 0.f, l1 = 0.f;

    for (int j = 0; j < 32; j++) {
        CP_WAIT1();
        __syncthreads();
        const uint32_t sk = smK + (j & 1) * 17408;
        const uint32_t sv = smV + (j & 1) * 17408;

        // ---- S = Q K^T : 16 rows x 64 keys, 8 k16 steps ----
        float s[8][4];
        #pragma unroll
        for (int t = 0; t < 8; t++)
            #pragma unroll
            for (int e = 0; e < 4; e++) s[t][e] = 0.f;
        #pragma unroll
        for (int ks = 0; ks < 8; ks++) {
            uint32_t qa[4];
            {
                uint32_t row = wr + lb3 * 8 + l7;
                ldsm4(qa, smQ + row * 272 + (ks * 2 + lb4) * 16);
            }
            #pragma unroll
            for (int nt = 0; nt < 4; nt++) {
                uint32_t kf[4];
                uint32_t row = nt * 16 + lb4 * 8 + l7;
                ldsm4(kf, sk + row * 272 + (ks * 2 + lb3) * 16);
                mma_h(s[nt * 2],     qa, kf[0], kf[1]);
                mma_h(s[nt * 2 + 1], qa, kf[2], kf[3]);
            }
        }

        // ---- online softmax (rows wr+g, wr+g+8) ----
        float tm0 = -1e30f, tm1 = -1e30f;
        #pragma unroll
        for (int t = 0; t < 8; t++) {
            s[t][0] *= isq; s[t][1] *= isq; s[t][2] *= isq; s[t][3] *= isq;
            tm0 = fmaxf(tm0, fmaxf(s[t][0], s[t][1]));
            tm1 = fmaxf(tm1, fmaxf(s[t][2], s[t][3]));
        }
        tm0 = quadMax(tm0); tm1 = quadMax(tm1);
        float mn0 = fmaxf(m0, tm0), mn1 = fmaxf(m1, tm1);
        float sc0 = __expf(m0 - mn0), sc1 = __expf(m1 - mn1);
        m0 = mn0; m1 = mn1;
        float ls0 = 0.f, ls1 = 0.f;
        uint32_t ah[8][2];
        #pragma unroll
        for (int t = 0; t < 8; t++) {
            s[t][0] = __expf(s[t][0] - mn0);
            s[t][1] = __expf(s[t][1] - mn0);
            s[t][2] = __expf(s[t][2] - mn1);
            s[t][3] = __expf(s[t][3] - mn1);
            ls0 += s[t][0] + s[t][1];
            ls1 += s[t][2] + s[t][3];
            ah[t][0] = h2u(__floats2half2_rn(s[t][0], s[t][1]));
            ah[t][1] = h2u(__floats2half2_rn(s[t][2], s[t][3]));
        }
        l0 = l0 * sc0 + ls0;
        l1 = l1 * sc1 + ls1;
        #pragma unroll
        for (int f = 0; f < 16; f++) {
            o[f][0] *= sc0; o[f][1] *= sc0;
            o[f][2] *= sc1; o[f][3] *= sc1;
        }

        // ---- O += P V : 4 k16 steps over keys, 16 n8 tiles over d ----
        #pragma unroll
        for (int kv = 0; kv < 4; kv++) {
            uint32_t pa[4] = { ah[2*kv][0], ah[2*kv][1], ah[2*kv+1][0], ah[2*kv+1][1] };
            #pragma unroll
            for (int nt2 = 0; nt2 < 8; nt2++) {
                uint32_t vf[4];
                uint32_t row = kv * 16 + lb3 * 8 + l7;
                ldsm4t(vf, sv + row * 272 + (nt2 * 2 + lb4) * 16);
                mma_h(o[nt2 * 2],     pa, vf[0], vf[1]);
                mma_h(o[nt2 * 2 + 1], pa, vf[2], vf[3]);
            }
        }
        __syncthreads();
        if (j < 30) stage(j & 1, j + 2);
        CP_COMMIT();
    }

    // ---- epilogue: out = q + O / l ----
    l0 = quadSum(l0); l1 = quadSum(l1);
    const float i0 = 1.f / l0, i1 = 1.f / l1;
    const int r0 = wr + g, r1 = wr + g + 8;
    #pragma unroll
    for (int nf = 0; nf < 16; nf++) {
        int c = nf * 8 + 2 * tg;
        float2 q0 = __half22float2(*(const __half2*)(qp + (long)r0 * DMODEL + c));
        float2 q1 = __half22float2(*(const __half2*)(qp + (long)r1 * DMODEL + c));
        *(float2*)(op + (long)r0 * DMODEL + c) =
            make_float2(q0.x + o[nf][0] * i0, q0.y + o[nf][1] * i0);
        *(float2*)(op + (long)r1 * DMODEL + c) =
            make_float2(q1.x + o[nf][2] * i1, q1.y + o[nf][3] * i1);
    }
}

// ---------------------------------------------------------------------------
// LayerNorm (rows of 1024). WH: also emit half copy.
// ---------------------------------------------------------------------------
template<bool WH>
__global__ __launch_bounds__(256)
void ln_kernel(const float* __restrict__ X, float* __restrict__ Y,
               __half* __restrict__ Yh,
               const float* __restrict__ gam, const float* __restrict__ bet)
{
    const float* x = X + (size_t)blockIdx.x * DMODEL;
    float*       y = Y + (size_t)blockIdx.x * DMODEL;
    __half*      yh = WH ? (Yh + (size_t)blockIdx.x * DMODEL) : nullptr;
    const int tid = threadIdx.x;
    float v[4];
    float s = 0.f, sq = 0.f;
    #pragma unroll
    for (int i = 0; i < 4; i++) {
        v[i] = x[i * 256 + tid];
        s  += v[i];
        sq += v[i] * v[i];
    }
    s  = warpSum(s);
    sq = warpSum(sq);
    __shared__ float a1[8], a2[8];
    if ((tid & 31) == 0) { a1[tid >> 5] = s; a2[tid >> 5] = sq; }
    __syncthreads();
    float S1 = ((a1[0] + a1[1]) + (a1[2] + a1[3])) + ((a1[4] + a1[5]) + (a1[6] + a1[7]));
    float S2 = ((a2[0] + a2[1]) + (a2[2] + a2[3])) + ((a2[4] + a2[5]) + (a2[6] + a2[7]));
    float mu  = S1 * (1.f / DMODEL);
    float var = S2 * (1.f / DMODEL) - mu * mu;
    float rs  = rsqrtf(var + 1e-5f);
    #pragma unroll
    for (int i = 0; i < 4; i++) {
        int c = i * 256 + tid;
        float r = (v[i] - mu) * rs * gam[c] + bet[c];
        y[c] = r;
        if (WH) yh[c] = __float2half_rn(r);
    }
}

// ---------------------------------------------------------------------------
extern "C" void kernel_launch(void* const* d_in, const int* in_sizes, int n_in,
                              void* d_out, int out_size)
{
    (void)in_sizes; (void)n_in; (void)out_size;
    const float* Q  = (const float*)d_in[0];
    const float* K_ = (const float*)d_in[1];
    const float* Wq = (const float*)d_in[2];
    const float* bq = (const float*)d_in[3];
    const float* Wk = (const float*)d_in[4];
    const float* bk = (const float*)d_in[5];
    const float* Wv = (const float*)d_in[6];
    const float* bv = (const float*)d_in[7];
    const float* Wo = (const float*)d_in[8];
    const float* bo = (const float*)d_in[9];
    const float* g0 = (const float*)d_in[10];
    const float* b0 = (const float*)d_in[11];
    const float* g1 = (const float*)d_in[12];
    const float* b1 = (const float*)d_in[13];
    float* out = (float*)d_out;

    __half *Qh, *Kh, *Wqh, *Wkh, *Wvh, *Woh, *qh, *kh, *vh, *x0h;
    float *att, *x0f;
    cudaGetSymbolAddress((void**)&Qh,  g_Qh);
    cudaGetSymbolAddress((void**)&Kh,  g_Kh);
    cudaGetSymbolAddress((void**)&Wqh, g_Wqh);
    cudaGetSymbolAddress((void**)&Wkh, g_Wkh);
    cudaGetSymbolAddress((void**)&Wvh, g_Wvh);
    cudaGetSymbolAddress((void**)&Woh, g_Woh);
    cudaGetSymbolAddress((void**)&qh,  g_qh);
    cudaGetSymbolAddress((void**)&kh,  g_kh);
    cudaGetSymbolAddress((void**)&vh,  g_vh);
    cudaGetSymbolAddress((void**)&x0h, g_x0h);
    cudaGetSymbolAddress((void**)&att, g_att);
    cudaGetSymbolAddress((void**)&x0f, g_x0f);

    const int GEMM_SMEM  = 65536;
    const int FLASH_SMEM = 104448;
    cudaFuncSetAttribute(gemm_h<0>, cudaFuncAttributeMaxDynamicSharedMemorySize, GEMM_SMEM);
    cudaFuncSetAttribute(gemm_h<3>, cudaFuncAttributeMaxDynamicSharedMemorySize, GEMM_SMEM);
    cudaFuncSetAttribute(flash_h,   cudaFuncAttributeMaxDynamicSharedMemorySize, FLASH_SMEM);

    const int NA = NROWS * DMODEL;     // 8M
    const int NW = DMODEL * DMODEL;    // 1M
    conv_f2h<<<NA / 1024, 256>>>(Q,  Qh,  NA);
    conv_f2h<<<NA / 1024, 256>>>(K_, Kh,  NA);
    conv_f2h<<<NW / 1024, 256>>>(Wq, Wqh, NW);
    conv_f2h<<<NW / 1024, 256>>>(Wk, Wkh, NW);
    conv_f2h<<<NW / 1024, 256>>>(Wv, Wvh, NW);
    conv_f2h<<<NW / 1024, 256>>>(Wo, Woh, NW);

    dim3 blk(256);
    dim3 gp(DMODEL / 128, NROWS / 128);          // (8, 64)
    gemm_h<0><<<gp, blk, GEMM_SMEM>>>(Qh, Wqh, qh, bq, nullptr);
    gemm_h<0><<<gp, blk, GEMM_SMEM>>>(Kh, Wkh, kh, bk, nullptr);
    gemm_h<0><<<gp, blk, GEMM_SMEM>>>(Kh, Wvh, vh, bv, nullptr);

    dim3 gf(NKEYS / 128, NBH);                   // (16, 32)
    flash_h<<<gf, blk, FLASH_SMEM>>>(qh, kh, vh, att);

    ln_kernel<true><<<NROWS, 256>>>(att, x0f, x0h, g0, b0);

    gemm_h<3><<<gp, blk, GEMM_SMEM>>>(x0h, Woh, att, bo, x0f);

    ln_kernel<false><<<NROWS, 256>>>(att, out, nullptr, g1, b1);
}